// round 13
// baseline (speedup 1.0000x reference)
#include <cuda_runtime.h>
#include <cstdint>

#define TT 2048
#define DD 2048
#define EE 8
#define HH 1408
#define HSD 2816

#define BK 16
#define ASTR 68    // As row stride (floats): [BK][64] padded
#define BSTR 132   // Bs row stride (floats): [BK][128] padded

__device__ __forceinline__ float silu(float g) { return g / (1.f + __expf(-g)); }

// ---------------- scratch ------------------------------------------------------
__device__ int   g_cnt[EE];
__device__ int   g_perm[EE * TT];
__device__ float g_cw[EE * TT];
__device__ float g_sgate[TT];
__device__ float g_h[(size_t)EE * TT * HH];
__device__ float g_hs[(size_t)TT * HSD];

// ---------------- kernel 0 -------------------------------------------------------
__global__ void zero_cnt_kernel() {
    if (threadIdx.x < EE) g_cnt[threadIdx.x] = 0;
}

// ---------------- kernel 1: router -----------------------------------------------
__global__ void __launch_bounds__(256) router_kernel(
    const float* __restrict__ x,
    const float* __restrict__ gate_w,
    const float* __restrict__ shgate_w)
{
    int t = blockIdx.x;
    const float* xr = x + (size_t)t * DD;
    float acc[9];
#pragma unroll
    for (int v = 0; v < 9; v++) acc[v] = 0.f;
    for (int j = threadIdx.x; j < DD; j += 256) {
        float xv = xr[j];
#pragma unroll
        for (int e = 0; e < EE; e++) acc[e] = fmaf(xv, gate_w[e * DD + j], acc[e]);
        acc[8] = fmaf(xv, shgate_w[j], acc[8]);
    }
#pragma unroll
    for (int o = 16; o > 0; o >>= 1) {
#pragma unroll
        for (int v = 0; v < 9; v++) acc[v] += __shfl_down_sync(0xffffffffu, acc[v], o);
    }
    __shared__ float sred[9][8];
    int lane = threadIdx.x & 31, wid = threadIdx.x >> 5;
    if (lane == 0) {
#pragma unroll
        for (int v = 0; v < 9; v++) sred[v][wid] = acc[v];
    }
    __syncthreads();
    if (threadIdx.x == 0) {
        float l[9];
#pragma unroll
        for (int v = 0; v < 9; v++) {
            float s = 0.f;
#pragma unroll
            for (int w = 0; w < 8; w++) s += sred[v][w];
            l[v] = s;
        }
        float m = l[0];
#pragma unroll
        for (int e = 1; e < EE; e++) m = fmaxf(m, l[e]);
        float p[EE];
#pragma unroll
        for (int e = 0; e < EE; e++) p[e] = expf(l[e] - m);
        int i0 = 0;
#pragma unroll
        for (int e = 1; e < EE; e++) if (p[e] > p[i0]) i0 = e;
        int i1 = (i0 == 0) ? 1 : 0;
#pragma unroll
        for (int e = 0; e < EE; e++) if (e != i0 && p[e] > p[i1]) i1 = e;
        float inv = 1.f / (p[i0] + p[i1]);
        int q0 = atomicAdd(&g_cnt[i0], 1);
        g_perm[i0 * TT + q0] = t;
        g_cw[i0 * TT + q0]   = p[i0] * inv;
        int q1 = atomicAdd(&g_cnt[i1], 1);
        g_perm[i1 * TT + q1] = t;
        g_cw[i1 * TT + q1]   = p[i1] * inv;
        g_sgate[t] = 1.f / (1.f + expf(-l[8]));
    }
}

// ===================== gate/up GEMM core (64-row tile, double-buffered) ===========
// block: 64 rows x (64 gate + 64 up cols), BK=16, 256 thr, thread tile 4x(4+4)
__device__ __forceinline__ void gateup_core(
    const float* arow,                       // this thread's A-row pointer (row ar)
    const float* wg, const float* wu, int Ndim, int colg0, int Kdim,
    float cg[4][4], float cu[4][4])
{
    __shared__ alignas(16) float As[2][BK][ASTR];   // [k][m] transposed, 64 m
    __shared__ alignas(16) float Bs[2][BK][BSTR];   // [k][0:64)=gate, [64:128)=up

    int tid = threadIdx.x;
    int tx = tid & 15, ty = tid >> 4;
    int ar  = tid >> 2;          // A loader row 0..63
    int akc = (tid & 3) << 2;    // A loader k quad
    int bk_ = tid >> 4;          // B loader k row 0..15
    int bn4 = (tid & 15) << 2;   // B loader n quad

    const int NS = Kdim / BK;

    // preload slab 0
    {
        float4 v = *(const float4*)(arow + akc);
        As[0][akc + 0][ar] = v.x; As[0][akc + 1][ar] = v.y;
        As[0][akc + 2][ar] = v.z; As[0][akc + 3][ar] = v.w;
        size_t goff = (size_t)bk_ * Ndim + colg0 + bn4;
        *(float4*)&Bs[0][bk_][bn4]      = *(const float4*)(wg + goff);
        *(float4*)&Bs[0][bk_][bn4 + 64] = *(const float4*)(wu + goff);
    }
    __syncthreads();

    for (int s = 0; s < NS; s++) {
        int cur = s & 1;
        float4 pa, pbg, pbu;
        if (s + 1 < NS) {
            int k1 = (s + 1) * BK;
            pa = *(const float4*)(arow + k1 + akc);
            size_t goff = (size_t)(k1 + bk_) * Ndim + colg0 + bn4;
            pbg = *(const float4*)(wg + goff);
            pbu = *(const float4*)(wu + goff);
        }
        const float (*Ac)[ASTR] = As[cur];
        const float (*Bc)[BSTR] = Bs[cur];
#pragma unroll
        for (int kk = 0; kk < BK; kk++) {
            float4 a  = *(const float4*)&Ac[kk][ty * 4];
            float4 bg = *(const float4*)&Bc[kk][tx * 4];
            float4 bu = *(const float4*)&Bc[kk][tx * 4 + 64];
            float av[4]  = { a.x, a.y, a.z, a.w };
            float bgv[4] = { bg.x, bg.y, bg.z, bg.w };
            float buv[4] = { bu.x, bu.y, bu.z, bu.w };
#pragma unroll
            for (int i = 0; i < 4; i++)
#pragma unroll
                for (int j = 0; j < 4; j++) {
                    cg[i][j] = fmaf(av[i], bgv[j], cg[i][j]);
                    cu[i][j] = fmaf(av[i], buv[j], cu[i][j]);
                }
        }
        if (s + 1 < NS) {
            int nxt = cur ^ 1;
            As[nxt][akc + 0][ar] = pa.x; As[nxt][akc + 1][ar] = pa.y;
            As[nxt][akc + 2][ar] = pa.z; As[nxt][akc + 3][ar] = pa.w;
            *(float4*)&Bs[nxt][bk_][bn4]      = pbg;
            *(float4*)&Bs[nxt][bk_][bn4 + 64] = pbu;
            __syncthreads();
        }
    }
}

// ---------------- expert gate/up --------------------------------------------------
__global__ void __launch_bounds__(256, 3) expert_gateup_kernel(
    const float* __restrict__ x,
    const float* __restrict__ w_gate,
    const float* __restrict__ w_up)
{
    int e = blockIdx.z;
    int nrows = g_cnt[e];
    int row0 = blockIdx.y * 64;
    if (row0 >= nrows) return;
    int colg0 = blockIdx.x * 64;
    const float* wg = w_gate + (size_t)e * DD * HH;
    const float* wu = w_up   + (size_t)e * DD * HH;

    int tid = threadIdx.x;
    int tx = tid & 15, ty = tid >> 4;
    int ar = tid >> 2;

    int pos = row0 + ar;
    int tok = (pos < nrows) ? g_perm[e * TT + pos] : g_perm[e * TT];

    float cg[4][4], cu[4][4];
#pragma unroll
    for (int i = 0; i < 4; i++)
#pragma unroll
        for (int j = 0; j < 4; j++) { cg[i][j] = 0.f; cu[i][j] = 0.f; }

    gateup_core(x + (size_t)tok * DD, wg, wu, HH, colg0, DD, cg, cu);

#pragma unroll
    for (int i = 0; i < 4; i++) {
        int p = row0 + ty * 4 + i;
        if (p < nrows) {
            float* o = g_h + ((size_t)e * TT + p) * HH + colg0 + tx * 4;
            float4 v;
            v.x = cu[i][0] * silu(cg[i][0]);
            v.y = cu[i][1] * silu(cg[i][1]);
            v.z = cu[i][2] * silu(cg[i][2]);
            v.w = cu[i][3] * silu(cg[i][3]);
            *(float4*)o = v;
        }
    }
}

// ---------------- shared gate/up --------------------------------------------------
__global__ void __launch_bounds__(256, 3) shared_gateup_kernel(
    const float* __restrict__ x,
    const float* __restrict__ shw_gate,
    const float* __restrict__ shw_up)
{
    int row0 = blockIdx.y * 64;
    int colg0 = blockIdx.x * 64;

    int tid = threadIdx.x;
    int tx = tid & 15, ty = tid >> 4;
    int ar = tid >> 2;

    float cg[4][4], cu[4][4];
#pragma unroll
    for (int i = 0; i < 4; i++)
#pragma unroll
        for (int j = 0; j < 4; j++) { cg[i][j] = 0.f; cu[i][j] = 0.f; }

    gateup_core(x + (size_t)(row0 + ar) * DD, shw_gate, shw_up, HSD, colg0, DD, cg, cu);

#pragma unroll
    for (int i = 0; i < 4; i++) {
        int p = row0 + ty * 4 + i;
        float* o = g_hs + (size_t)p * HSD + colg0 + tx * 4;
        float4 v;
        v.x = cu[i][0] * silu(cg[i][0]);
        v.y = cu[i][1] * silu(cg[i][1]);
        v.z = cu[i][2] * silu(cg[i][2]);
        v.w = cu[i][3] * silu(cg[i][3]);
        *(float4*)o = v;
    }
}

// ===================== down GEMM core (64-row tile, double-buffered) ===============
// block: 64 rows x 128 cols, BK=16, 256 thr, thread tile 4x8
__device__ __forceinline__ void down_core(
    const float* arow,
    const float* wd, int col0, int Kdim,
    float c[4][8])
{
    __shared__ alignas(16) float As[2][BK][ASTR];
    __shared__ alignas(16) float Bs[2][BK][BSTR];

    int tid = threadIdx.x;
    int tx = tid & 15, ty = tid >> 4;
    int ar  = tid >> 2;
    int akc = (tid & 3) << 2;
    int bk0 = tid >> 5;            // B loader: rows tid/32 and tid/32+8
    int bn4 = (tid & 31) << 2;

    const int NS = Kdim / BK;

    {
        float4 v = *(const float4*)(arow + akc);
        As[0][akc + 0][ar] = v.x; As[0][akc + 1][ar] = v.y;
        As[0][akc + 2][ar] = v.z; As[0][akc + 3][ar] = v.w;
        *(float4*)&Bs[0][bk0][bn4]     = *(const float4*)(wd + (size_t)bk0 * DD + col0 + bn4);
        *(float4*)&Bs[0][bk0 + 8][bn4] = *(const float4*)(wd + (size_t)(bk0 + 8) * DD + col0 + bn4);
    }
    __syncthreads();

    for (int s = 0; s < NS; s++) {
        int cur = s & 1;
        float4 pa, pb0, pb1;
        if (s + 1 < NS) {
            int k1 = (s + 1) * BK;
            pa = *(const float4*)(arow + k1 + akc);
            pb0 = *(const float4*)(wd + (size_t)(k1 + bk0) * DD + col0 + bn4);
            pb1 = *(const float4*)(wd + (size_t)(k1 + bk0 + 8) * DD + col0 + bn4);
        }
        const float (*Ac)[ASTR] = As[cur];
        const float (*Bc)[BSTR] = Bs[cur];
#pragma unroll
        for (int kk = 0; kk < BK; kk++) {
            float4 a  = *(const float4*)&Ac[kk][ty * 4];
            float4 b0 = *(const float4*)&Bc[kk][tx * 4];
            float4 b1 = *(const float4*)&Bc[kk][tx * 4 + 64];
            float av[4] = { a.x, a.y, a.z, a.w };
            float bv[8] = { b0.x, b0.y, b0.z, b0.w, b1.x, b1.y, b1.z, b1.w };
#pragma unroll
            for (int i = 0; i < 4; i++)
#pragma unroll
                for (int j = 0; j < 8; j++)
                    c[i][j] = fmaf(av[i], bv[j], c[i][j]);
        }
        if (s + 1 < NS) {
            int nxt = cur ^ 1;
            As[nxt][akc + 0][ar] = pa.x; As[nxt][akc + 1][ar] = pa.y;
            As[nxt][akc + 2][ar] = pa.z; As[nxt][akc + 3][ar] = pa.w;
            *(float4*)&Bs[nxt][bk0][bn4]     = pb0;
            *(float4*)&Bs[nxt][bk0 + 8][bn4] = pb1;
            __syncthreads();
        }
    }
}

// ---------------- shared down ------------------------------------------------------
__global__ void __launch_bounds__(256, 3) shared_down_kernel(
    const float* __restrict__ shw_down,
    float* __restrict__ out)
{
    int row0 = blockIdx.y * 64;
    int col0 = blockIdx.x * 128;

    int tid = threadIdx.x;
    int tx = tid & 15, ty = tid >> 4;
    int ar = tid >> 2;

    float c[4][8];
#pragma unroll
    for (int i = 0; i < 4; i++)
#pragma unroll
        for (int j = 0; j < 8; j++) c[i][j] = 0.f;

    down_core(g_hs + (size_t)(row0 + ar) * HSD, shw_down, col0, HSD, c);

#pragma unroll
    for (int i = 0; i < 4; i++) {
        int pos = row0 + ty * 4 + i;
        float sg = g_sgate[pos];
        float* op = out + (size_t)pos * DD + col0;
        float4 v0, v1;
        v0.x = sg * c[i][0]; v0.y = sg * c[i][1]; v0.z = sg * c[i][2]; v0.w = sg * c[i][3];
        v1.x = sg * c[i][4]; v1.y = sg * c[i][5]; v1.z = sg * c[i][6]; v1.w = sg * c[i][7];
        *(float4*)(op + tx * 4) = v0;
        *(float4*)(op + 64 + tx * 4) = v1;
    }
}

// ---------------- expert down -------------------------------------------------------
__global__ void __launch_bounds__(256, 3) expert_down_kernel(
    const float* __restrict__ w_down,
    float* __restrict__ out)
{
    int e = blockIdx.z;
    int nrows = g_cnt[e];
    int row0 = blockIdx.y * 64;
    if (row0 >= nrows) return;
    int col0 = blockIdx.x * 128;
    const float* wd = w_down + (size_t)e * HH * DD;

    int tid = threadIdx.x;
    int tx = tid & 15, ty = tid >> 4;
    int ar = tid >> 2;

    int apos = row0 + ar;
    const float* arow = g_h + ((size_t)e * TT + apos) * HH;

    float c[4][8];
#pragma unroll
    for (int i = 0; i < 4; i++)
#pragma unroll
        for (int j = 0; j < 8; j++) c[i][j] = 0.f;

    down_core(arow, wd, col0, HH, c);

#pragma unroll
    for (int i = 0; i < 4; i++) {
        int pos = row0 + ty * 4 + i;
        if (pos < nrows) {
            int tok = g_perm[e * TT + pos];
            float cw = g_cw[e * TT + pos];
            float* op = out + (size_t)tok * DD + col0;
#pragma unroll
            for (int j = 0; j < 4; j++) {
                atomicAdd(op + tx * 4 + j,      cw * c[i][j]);
                atomicAdd(op + 64 + tx * 4 + j, cw * c[i][j + 4]);
            }
        }
    }
}

// ---------------- launch ----------------------------------------------------------
extern "C" void kernel_launch(void* const* d_in, const int* in_sizes, int n_in,
                              void* d_out, int out_size)
{
    const float* x        = (const float*)d_in[0];
    const float* gate_w   = (const float*)d_in[1];
    const float* w_gate   = (const float*)d_in[2];
    const float* w_up     = (const float*)d_in[3];
    const float* w_down   = (const float*)d_in[4];
    const float* shgate_w = (const float*)d_in[5];
    const float* shw_gate = (const float*)d_in[6];
    const float* shw_up   = (const float*)d_in[7];
    const float* shw_down = (const float*)d_in[8];
    float* out = (float*)d_out;

    zero_cnt_kernel<<<1, 32>>>();
    router_kernel<<<TT, 256>>>(x, gate_w, shgate_w);
    expert_gateup_kernel<<<dim3(HH / 64, TT / 64, EE), 256>>>(x, w_gate, w_up);
    shared_gateup_kernel<<<dim3(HSD / 64, TT / 64), 256>>>(x, shw_gate, shw_up);
    shared_down_kernel<<<dim3(DD / 128, TT / 64), 256>>>(shw_down, out);
    expert_down_kernel<<<dim3(DD / 128, TT / 64, EE), 256>>>(w_down, out);
}

// round 14
// speedup vs baseline: 1.0533x; 1.0533x over previous
#include <cuda_runtime.h>
#include <cstdint>

#define TT 2048
#define DD 2048
#define EE 8
#define HH 1408
#define HSD 2816

#define BK 16
#define SSTR 132   // smem row stride (floats) for [BK][128] tiles

// merged gateup grid decomposition
#define EXPX 22            // HH/64
#define EXPY 16            // TT/128
#define EXP_BLKS (EXPX * EXPY * EE)   // 2816
#define SHX 44             // HSD/64
#define SH_BLKS (SHX * 16)            // 704
#define GU_BLKS (EXP_BLKS + SH_BLKS)  // 3520

__device__ __forceinline__ float silu(float g) { return g / (1.f + __expf(-g)); }

// ---------------- scratch ------------------------------------------------------
__device__ int   g_cnt[EE];
__device__ int   g_perm[EE * TT];
__device__ float g_cw[EE * TT];
__device__ float g_sgate[TT];
__device__ float g_h[(size_t)EE * TT * HH];
__device__ float g_hs[(size_t)TT * HSD];

// ---------------- kernel 0 -------------------------------------------------------
__global__ void zero_cnt_kernel() {
    if (threadIdx.x < EE) g_cnt[threadIdx.x] = 0;
}

// ---------------- kernel 1: router -----------------------------------------------
__global__ void __launch_bounds__(256) router_kernel(
    const float* __restrict__ x,
    const float* __restrict__ gate_w,
    const float* __restrict__ shgate_w)
{
    int t = blockIdx.x;
    const float* xr = x + (size_t)t * DD;
    float acc[9];
#pragma unroll
    for (int v = 0; v < 9; v++) acc[v] = 0.f;
    for (int j = threadIdx.x; j < DD; j += 256) {
        float xv = xr[j];
#pragma unroll
        for (int e = 0; e < EE; e++) acc[e] = fmaf(xv, gate_w[e * DD + j], acc[e]);
        acc[8] = fmaf(xv, shgate_w[j], acc[8]);
    }
#pragma unroll
    for (int o = 16; o > 0; o >>= 1) {
#pragma unroll
        for (int v = 0; v < 9; v++) acc[v] += __shfl_down_sync(0xffffffffu, acc[v], o);
    }
    __shared__ float sred[9][8];
    int lane = threadIdx.x & 31, wid = threadIdx.x >> 5;
    if (lane == 0) {
#pragma unroll
        for (int v = 0; v < 9; v++) sred[v][wid] = acc[v];
    }
    __syncthreads();
    if (threadIdx.x == 0) {
        float l[9];
#pragma unroll
        for (int v = 0; v < 9; v++) {
            float s = 0.f;
#pragma unroll
            for (int w = 0; w < 8; w++) s += sred[v][w];
            l[v] = s;
        }
        float m = l[0];
#pragma unroll
        for (int e = 1; e < EE; e++) m = fmaxf(m, l[e]);
        float p[EE];
#pragma unroll
        for (int e = 0; e < EE; e++) p[e] = expf(l[e] - m);
        int i0 = 0;
#pragma unroll
        for (int e = 1; e < EE; e++) if (p[e] > p[i0]) i0 = e;
        int i1 = (i0 == 0) ? 1 : 0;
#pragma unroll
        for (int e = 0; e < EE; e++) if (e != i0 && p[e] > p[i1]) i1 = e;
        float inv = 1.f / (p[i0] + p[i1]);
        int q0 = atomicAdd(&g_cnt[i0], 1);
        g_perm[i0 * TT + q0] = t;
        g_cw[i0 * TT + q0]   = p[i0] * inv;
        int q1 = atomicAdd(&g_cnt[i1], 1);
        g_perm[i1 * TT + q1] = t;
        g_cw[i1 * TT + q1]   = p[i1] * inv;
        g_sgate[t] = 1.f / (1.f + expf(-l[8]));
    }
}

// ===================== merged gate/up GEMM (expert + shared roles) =================
// block: 128 rows x (64 gate + 64 up cols), BK=16, 256 thr, 8x8 thread tile
__global__ void __launch_bounds__(256, 2) gateup_merged_kernel(
    const float* __restrict__ x,
    const float* __restrict__ w_gate,
    const float* __restrict__ w_up,
    const float* __restrict__ shw_gate,
    const float* __restrict__ shw_up)
{
    __shared__ alignas(16) float As[2][BK][SSTR];
    __shared__ alignas(16) float Bs[2][BK][SSTR];

    int bid = blockIdx.x;
    bool isExp = (bid < EXP_BLKS);

    int e = 0, row0, colg0, nrows, Ndim;
    const float *wg, *wu;
    if (isExp) {
        e = bid / (EXPX * EXPY);
        int rem = bid % (EXPX * EXPY);
        row0 = (rem / EXPX) * 128;
        colg0 = (rem % EXPX) * 64;
        nrows = g_cnt[e];
        if (row0 >= nrows) return;
        wg = w_gate + (size_t)e * DD * HH;
        wu = w_up   + (size_t)e * DD * HH;
        Ndim = HH;
    } else {
        int sid = bid - EXP_BLKS;
        row0 = (sid / SHX) * 128;
        colg0 = (sid % SHX) * 64;
        nrows = TT;
        wg = shw_gate; wu = shw_up;
        Ndim = HSD;
    }

    int tid = threadIdx.x;
    int tx = tid & 15, ty = tid >> 4;
    int bk_ = tid >> 4;
    int bn4 = (tid & 15) << 2;
    int ar  = tid >> 2;
    int akc = (tid & 3) << 2;

    // A-row pointers for this thread's loader rows (ar, ar+64)
    const float* arow0;
    const float* arow1;
    {
        int pos0 = row0 + ar, pos1 = row0 + ar + 64;
        if (isExp) {
            int tok0 = (pos0 < nrows) ? g_perm[e * TT + pos0] : g_perm[e * TT];
            int tok1 = (pos1 < nrows) ? g_perm[e * TT + pos1] : g_perm[e * TT];
            arow0 = x + (size_t)tok0 * DD;
            arow1 = x + (size_t)tok1 * DD;
        } else {
            arow0 = x + (size_t)pos0 * DD;
            arow1 = x + (size_t)pos1 * DD;
        }
    }

    float cg[8][4], cu[8][4];
#pragma unroll
    for (int i = 0; i < 8; i++)
#pragma unroll
        for (int j = 0; j < 4; j++) { cg[i][j] = 0.f; cu[i][j] = 0.f; }

    const int NS = DD / BK;

    // preload slab 0
    {
        float4 v0 = *(const float4*)(arow0 + akc);
        float4 v1 = *(const float4*)(arow1 + akc);
        As[0][akc + 0][ar] = v0.x; As[0][akc + 1][ar] = v0.y;
        As[0][akc + 2][ar] = v0.z; As[0][akc + 3][ar] = v0.w;
        As[0][akc + 0][ar + 64] = v1.x; As[0][akc + 1][ar + 64] = v1.y;
        As[0][akc + 2][ar + 64] = v1.z; As[0][akc + 3][ar + 64] = v1.w;
        size_t goff = (size_t)bk_ * Ndim + colg0 + bn4;
        *(float4*)&Bs[0][bk_][bn4]      = *(const float4*)(wg + goff);
        *(float4*)&Bs[0][bk_][bn4 + 64] = *(const float4*)(wu + goff);
    }
    __syncthreads();

    for (int s = 0; s < NS; s++) {
        int cur = s & 1;
        float4 pa0, pa1, pbg, pbu;
        if (s + 1 < NS) {
            int k1 = (s + 1) * BK;
            pa0 = *(const float4*)(arow0 + k1 + akc);
            pa1 = *(const float4*)(arow1 + k1 + akc);
            size_t goff = (size_t)(k1 + bk_) * Ndim + colg0 + bn4;
            pbg = *(const float4*)(wg + goff);
            pbu = *(const float4*)(wu + goff);
        }
        const float (*Ac)[SSTR] = As[cur];
        const float (*Bc)[SSTR] = Bs[cur];
#pragma unroll
        for (int kk = 0; kk < BK; kk++) {
            float4 a0 = *(const float4*)&Ac[kk][ty * 4];
            float4 a1 = *(const float4*)&Ac[kk][ty * 4 + 64];
            float4 bg = *(const float4*)&Bc[kk][tx * 4];
            float4 bu = *(const float4*)&Bc[kk][tx * 4 + 64];
            float av[8] = { a0.x, a0.y, a0.z, a0.w, a1.x, a1.y, a1.z, a1.w };
            float bgv[4] = { bg.x, bg.y, bg.z, bg.w };
            float buv[4] = { bu.x, bu.y, bu.z, bu.w };
#pragma unroll
            for (int i = 0; i < 8; i++)
#pragma unroll
                for (int j = 0; j < 4; j++) {
                    cg[i][j] = fmaf(av[i], bgv[j], cg[i][j]);
                    cu[i][j] = fmaf(av[i], buv[j], cu[i][j]);
                }
        }
        if (s + 1 < NS) {
            int nxt = cur ^ 1;
            As[nxt][akc + 0][ar] = pa0.x; As[nxt][akc + 1][ar] = pa0.y;
            As[nxt][akc + 2][ar] = pa0.z; As[nxt][akc + 3][ar] = pa0.w;
            As[nxt][akc + 0][ar + 64] = pa1.x; As[nxt][akc + 1][ar + 64] = pa1.y;
            As[nxt][akc + 2][ar + 64] = pa1.z; As[nxt][akc + 3][ar + 64] = pa1.w;
            *(float4*)&Bs[nxt][bk_][bn4]      = pbg;
            *(float4*)&Bs[nxt][bk_][bn4 + 64] = pbu;
            __syncthreads();
        }
    }

    // epilogue: silu(g)*u
#pragma unroll
    for (int i = 0; i < 8; i++) {
        int pos = row0 + (i < 4 ? ty * 4 + i : 64 + ty * 4 + (i - 4));
        if (!isExp || pos < nrows) {
            float* o = isExp ? (g_h + ((size_t)e * TT + pos) * HH + colg0 + tx * 4)
                             : (g_hs + (size_t)pos * HSD + colg0 + tx * 4);
            float4 v;
            v.x = cu[i][0] * silu(cg[i][0]);
            v.y = cu[i][1] * silu(cg[i][1]);
            v.z = cu[i][2] * silu(cg[i][2]);
            v.w = cu[i][3] * silu(cg[i][3]);
            *(float4*)o = v;
        }
    }
}

// ===================== down GEMM core (double-buffered, from R12) ==================
__device__ __forceinline__ void down_core(
    const float* arow0, const float* arow1,
    const float* wd, int col0, int Kdim,
    float c[8][8])
{
    __shared__ alignas(16) float As[2][BK][SSTR];
    __shared__ alignas(16) float Bs[2][BK][SSTR];

    int tid = threadIdx.x;
    int tx = tid & 15, ty = tid >> 4;
    int ar  = tid >> 2;
    int akc = (tid & 3) << 2;
    int bk0 = tid >> 5;
    int bn4 = (tid & 31) << 2;

    const int NS = Kdim / BK;

    {
        float4 v0 = *(const float4*)(arow0 + akc);
        float4 v1 = *(const float4*)(arow1 + akc);
        As[0][akc + 0][ar] = v0.x; As[0][akc + 1][ar] = v0.y;
        As[0][akc + 2][ar] = v0.z; As[0][akc + 3][ar] = v0.w;
        As[0][akc + 0][ar + 64] = v1.x; As[0][akc + 1][ar + 64] = v1.y;
        As[0][akc + 2][ar + 64] = v1.z; As[0][akc + 3][ar + 64] = v1.w;
        *(float4*)&Bs[0][bk0][bn4]     = *(const float4*)(wd + (size_t)bk0 * DD + col0 + bn4);
        *(float4*)&Bs[0][bk0 + 8][bn4] = *(const float4*)(wd + (size_t)(bk0 + 8) * DD + col0 + bn4);
    }
    __syncthreads();

    for (int s = 0; s < NS; s++) {
        int cur = s & 1;
        float4 pa0, pa1, pb0, pb1;
        if (s + 1 < NS) {
            int k1 = (s + 1) * BK;
            pa0 = *(const float4*)(arow0 + k1 + akc);
            pa1 = *(const float4*)(arow1 + k1 + akc);
            pb0 = *(const float4*)(wd + (size_t)(k1 + bk0) * DD + col0 + bn4);
            pb1 = *(const float4*)(wd + (size_t)(k1 + bk0 + 8) * DD + col0 + bn4);
        }
        const float (*Ac)[SSTR] = As[cur];
        const float (*Bc)[SSTR] = Bs[cur];
#pragma unroll
        for (int kk = 0; kk < BK; kk++) {
            float4 a0 = *(const float4*)&Ac[kk][ty * 4];
            float4 a1 = *(const float4*)&Ac[kk][ty * 4 + 64];
            float4 b0 = *(const float4*)&Bc[kk][tx * 4];
            float4 b1 = *(const float4*)&Bc[kk][tx * 4 + 64];
            float av[8] = { a0.x, a0.y, a0.z, a0.w, a1.x, a1.y, a1.z, a1.w };
            float bv[8] = { b0.x, b0.y, b0.z, b0.w, b1.x, b1.y, b1.z, b1.w };
#pragma unroll
            for (int i = 0; i < 8; i++)
#pragma unroll
                for (int j = 0; j < 8; j++)
                    c[i][j] = fmaf(av[i], bv[j], c[i][j]);
        }
        if (s + 1 < NS) {
            int nxt = cur ^ 1;
            As[nxt][akc + 0][ar] = pa0.x; As[nxt][akc + 1][ar] = pa0.y;
            As[nxt][akc + 2][ar] = pa0.z; As[nxt][akc + 3][ar] = pa0.w;
            As[nxt][akc + 0][ar + 64] = pa1.x; As[nxt][akc + 1][ar + 64] = pa1.y;
            As[nxt][akc + 2][ar + 64] = pa1.z; As[nxt][akc + 3][ar + 64] = pa1.w;
            *(float4*)&Bs[nxt][bk0][bn4]     = pb0;
            *(float4*)&Bs[nxt][bk0 + 8][bn4] = pb1;
            __syncthreads();
        }
    }
}

// ---------------- shared down ------------------------------------------------------
__global__ void __launch_bounds__(256, 2) shared_down_kernel(
    const float* __restrict__ shw_down,
    float* __restrict__ out)
{
    int row0 = blockIdx.y * 128;
    int col0 = blockIdx.x * 128;

    int tid = threadIdx.x;
    int tx = tid & 15, ty = tid >> 4;
    int ar = tid >> 2;

    float c[8][8];
#pragma unroll
    for (int i = 0; i < 8; i++)
#pragma unroll
        for (int j = 0; j < 8; j++) c[i][j] = 0.f;

    down_core(g_hs + (size_t)(row0 + ar) * HSD, g_hs + (size_t)(row0 + ar + 64) * HSD,
              shw_down, col0, HSD, c);

#pragma unroll
    for (int i = 0; i < 8; i++) {
        int pos = row0 + (i < 4 ? ty * 4 + i : 64 + ty * 4 + (i - 4));
        float sg = g_sgate[pos];
        float* op = out + (size_t)pos * DD + col0;
        float4 v0, v1;
        v0.x = sg * c[i][0]; v0.y = sg * c[i][1]; v0.z = sg * c[i][2]; v0.w = sg * c[i][3];
        v1.x = sg * c[i][4]; v1.y = sg * c[i][5]; v1.z = sg * c[i][6]; v1.w = sg * c[i][7];
        *(float4*)(op + tx * 4) = v0;
        *(float4*)(op + 64 + tx * 4) = v1;
    }
}

// ---------------- expert down -------------------------------------------------------
__global__ void __launch_bounds__(256, 2) expert_down_kernel(
    const float* __restrict__ w_down,
    float* __restrict__ out)
{
    int e = blockIdx.z;
    int nrows = g_cnt[e];
    int row0 = blockIdx.y * 128;
    if (row0 >= nrows) return;
    int col0 = blockIdx.x * 128;
    const float* wd = w_down + (size_t)e * HH * DD;

    int tid = threadIdx.x;
    int tx = tid & 15, ty = tid >> 4;
    int ar = tid >> 2;

    float c[8][8];
#pragma unroll
    for (int i = 0; i < 8; i++)
#pragma unroll
        for (int j = 0; j < 8; j++) c[i][j] = 0.f;

    down_core(g_h + ((size_t)e * TT + row0 + ar) * HH,
              g_h + ((size_t)e * TT + row0 + ar + 64) * HH,
              wd, col0, HH, c);

#pragma unroll
    for (int i = 0; i < 8; i++) {
        int pos = row0 + (i < 4 ? ty * 4 + i : 64 + ty * 4 + (i - 4));
        if (pos < nrows) {
            int tok = g_perm[e * TT + pos];
            float cw = g_cw[e * TT + pos];
            float* op = out + (size_t)tok * DD + col0;
#pragma unroll
            for (int j = 0; j < 4; j++) {
                atomicAdd(op + tx * 4 + j,      cw * c[i][j]);
                atomicAdd(op + 64 + tx * 4 + j, cw * c[i][j + 4]);
            }
        }
    }
}

// ---------------- launch ----------------------------------------------------------
extern "C" void kernel_launch(void* const* d_in, const int* in_sizes, int n_in,
                              void* d_out, int out_size)
{
    const float* x        = (const float*)d_in[0];
    const float* gate_w   = (const float*)d_in[1];
    const float* w_gate   = (const float*)d_in[2];
    const float* w_up     = (const float*)d_in[3];
    const float* w_down   = (const float*)d_in[4];
    const float* shgate_w = (const float*)d_in[5];
    const float* shw_gate = (const float*)d_in[6];
    const float* shw_up   = (const float*)d_in[7];
    const float* shw_down = (const float*)d_in[8];
    float* out = (float*)d_out;

    zero_cnt_kernel<<<1, 32>>>();
    router_kernel<<<TT, 256>>>(x, gate_w, shgate_w);
    gateup_merged_kernel<<<GU_BLKS, 256>>>(x, w_gate, w_up, shw_gate, shw_up);
    shared_down_kernel<<<dim3(DD / 128, TT / 128), 256>>>(shw_down, out);
    expert_down_kernel<<<dim3(DD / 128, TT / 128, EE), 256>>>(w_down, out);
}

// round 15
// speedup vs baseline: 1.0680x; 1.0140x over previous
#include <cuda_runtime.h>
#include <cstdint>

#define TT 2048
#define DD 2048
#define EE 8
#define HH 1408
#define HSD 2816

#define BK 16
#define SSTR 132   // smem row stride (floats) for [BK][128] tiles

// merged gateup grid decomposition
#define EXPX 22            // HH/64
#define EXPY 16            // TT/128
#define EXP_BLKS (EXPX * EXPY * EE)   // 2816
#define SHX 44             // HSD/64
#define SH_BLKS (SHX * 16)            // 704
#define GU_BLKS (EXP_BLKS + SH_BLKS)  // 3520

// merged down grid decomposition (block = 128 rows x 128 cols)
#define DNX 16             // DD/128
#define DNY 16             // TT/128
#define DEXP_BLKS (DNX * DNY * EE)    // 2048
#define DSH_BLKS (DNX * DNY)          // 256
#define DN_BLKS (DEXP_BLKS + DSH_BLKS)

__device__ __forceinline__ float silu(float g) { return g / (1.f + __expf(-g)); }

// ---------------- scratch ------------------------------------------------------
__device__ int   g_cnt[EE];
__device__ int   g_perm[EE * TT];
__device__ float g_cw[EE * TT];
__device__ float g_sgate[TT];
__device__ float g_h[(size_t)EE * TT * HH];
__device__ float g_hs[(size_t)TT * HSD];

// ---------------- kernel 0 -------------------------------------------------------
__global__ void zero_cnt_kernel() {
    if (threadIdx.x < EE) g_cnt[threadIdx.x] = 0;
}

// ---------------- kernel 1: router -----------------------------------------------
__global__ void __launch_bounds__(256) router_kernel(
    const float* __restrict__ x,
    const float* __restrict__ gate_w,
    const float* __restrict__ shgate_w)
{
    int t = blockIdx.x;
    const float* xr = x + (size_t)t * DD;
    float acc[9];
#pragma unroll
    for (int v = 0; v < 9; v++) acc[v] = 0.f;
    for (int j = threadIdx.x; j < DD; j += 256) {
        float xv = xr[j];
#pragma unroll
        for (int e = 0; e < EE; e++) acc[e] = fmaf(xv, gate_w[e * DD + j], acc[e]);
        acc[8] = fmaf(xv, shgate_w[j], acc[8]);
    }
#pragma unroll
    for (int o = 16; o > 0; o >>= 1) {
#pragma unroll
        for (int v = 0; v < 9; v++) acc[v] += __shfl_down_sync(0xffffffffu, acc[v], o);
    }
    __shared__ float sred[9][8];
    int lane = threadIdx.x & 31, wid = threadIdx.x >> 5;
    if (lane == 0) {
#pragma unroll
        for (int v = 0; v < 9; v++) sred[v][wid] = acc[v];
    }
    __syncthreads();
    if (threadIdx.x == 0) {
        float l[9];
#pragma unroll
        for (int v = 0; v < 9; v++) {
            float s = 0.f;
#pragma unroll
            for (int w = 0; w < 8; w++) s += sred[v][w];
            l[v] = s;
        }
        float m = l[0];
#pragma unroll
        for (int e = 1; e < EE; e++) m = fmaxf(m, l[e]);
        float p[EE];
#pragma unroll
        for (int e = 0; e < EE; e++) p[e] = expf(l[e] - m);
        int i0 = 0;
#pragma unroll
        for (int e = 1; e < EE; e++) if (p[e] > p[i0]) i0 = e;
        int i1 = (i0 == 0) ? 1 : 0;
#pragma unroll
        for (int e = 0; e < EE; e++) if (e != i0 && p[e] > p[i1]) i1 = e;
        float inv = 1.f / (p[i0] + p[i1]);
        int q0 = atomicAdd(&g_cnt[i0], 1);
        g_perm[i0 * TT + q0] = t;
        g_cw[i0 * TT + q0]   = p[i0] * inv;
        int q1 = atomicAdd(&g_cnt[i1], 1);
        g_perm[i1 * TT + q1] = t;
        g_cw[i1 * TT + q1]   = p[i1] * inv;
        g_sgate[t] = 1.f / (1.f + expf(-l[8]));
    }
}

// ===================== merged gate/up GEMM (expert + shared roles) =================
__global__ void __launch_bounds__(256, 2) gateup_merged_kernel(
    const float* __restrict__ x,
    const float* __restrict__ w_gate,
    const float* __restrict__ w_up,
    const float* __restrict__ shw_gate,
    const float* __restrict__ shw_up)
{
    __shared__ alignas(16) float As[2][BK][SSTR];
    __shared__ alignas(16) float Bs[2][BK][SSTR];

    int bid = blockIdx.x;
    bool isExp = (bid < EXP_BLKS);

    int e = 0, row0, colg0, nrows, Ndim;
    const float *wg, *wu;
    if (isExp) {
        e = bid / (EXPX * EXPY);
        int rem = bid % (EXPX * EXPY);
        row0 = (rem / EXPX) * 128;
        colg0 = (rem % EXPX) * 64;
        nrows = g_cnt[e];
        if (row0 >= nrows) return;
        wg = w_gate + (size_t)e * DD * HH;
        wu = w_up   + (size_t)e * DD * HH;
        Ndim = HH;
    } else {
        int sid = bid - EXP_BLKS;
        row0 = (sid / SHX) * 128;
        colg0 = (sid % SHX) * 64;
        nrows = TT;
        wg = shw_gate; wu = shw_up;
        Ndim = HSD;
    }

    int tid = threadIdx.x;
    int tx = tid & 15, ty = tid >> 4;
    int bk_ = tid >> 4;
    int bn4 = (tid & 15) << 2;
    int ar  = tid >> 2;
    int akc = (tid & 3) << 2;

    const float* arow0;
    const float* arow1;
    {
        int pos0 = row0 + ar, pos1 = row0 + ar + 64;
        if (isExp) {
            int tok0 = (pos0 < nrows) ? g_perm[e * TT + pos0] : g_perm[e * TT];
            int tok1 = (pos1 < nrows) ? g_perm[e * TT + pos1] : g_perm[e * TT];
            arow0 = x + (size_t)tok0 * DD;
            arow1 = x + (size_t)tok1 * DD;
        } else {
            arow0 = x + (size_t)pos0 * DD;
            arow1 = x + (size_t)pos1 * DD;
        }
    }

    float cg[8][4], cu[8][4];
#pragma unroll
    for (int i = 0; i < 8; i++)
#pragma unroll
        for (int j = 0; j < 4; j++) { cg[i][j] = 0.f; cu[i][j] = 0.f; }

    const int NS = DD / BK;

    {
        float4 v0 = *(const float4*)(arow0 + akc);
        float4 v1 = *(const float4*)(arow1 + akc);
        As[0][akc + 0][ar] = v0.x; As[0][akc + 1][ar] = v0.y;
        As[0][akc + 2][ar] = v0.z; As[0][akc + 3][ar] = v0.w;
        As[0][akc + 0][ar + 64] = v1.x; As[0][akc + 1][ar + 64] = v1.y;
        As[0][akc + 2][ar + 64] = v1.z; As[0][akc + 3][ar + 64] = v1.w;
        size_t goff = (size_t)bk_ * Ndim + colg0 + bn4;
        *(float4*)&Bs[0][bk_][bn4]      = *(const float4*)(wg + goff);
        *(float4*)&Bs[0][bk_][bn4 + 64] = *(const float4*)(wu + goff);
    }
    __syncthreads();

    for (int s = 0; s < NS; s++) {
        int cur = s & 1;
        float4 pa0, pa1, pbg, pbu;
        if (s + 1 < NS) {
            int k1 = (s + 1) * BK;
            pa0 = *(const float4*)(arow0 + k1 + akc);
            pa1 = *(const float4*)(arow1 + k1 + akc);
            size_t goff = (size_t)(k1 + bk_) * Ndim + colg0 + bn4;
            pbg = *(const float4*)(wg + goff);
            pbu = *(const float4*)(wu + goff);
        }
        const float (*Ac)[SSTR] = As[cur];
        const float (*Bc)[SSTR] = Bs[cur];
#pragma unroll
        for (int kk = 0; kk < BK; kk++) {
            float4 a0 = *(const float4*)&Ac[kk][ty * 4];
            float4 a1 = *(const float4*)&Ac[kk][ty * 4 + 64];
            float4 bg = *(const float4*)&Bc[kk][tx * 4];
            float4 bu = *(const float4*)&Bc[kk][tx * 4 + 64];
            float av[8] = { a0.x, a0.y, a0.z, a0.w, a1.x, a1.y, a1.z, a1.w };
            float bgv[4] = { bg.x, bg.y, bg.z, bg.w };
            float buv[4] = { bu.x, bu.y, bu.z, bu.w };
#pragma unroll
            for (int i = 0; i < 8; i++)
#pragma unroll
                for (int j = 0; j < 4; j++) {
                    cg[i][j] = fmaf(av[i], bgv[j], cg[i][j]);
                    cu[i][j] = fmaf(av[i], buv[j], cu[i][j]);
                }
        }
        if (s + 1 < NS) {
            int nxt = cur ^ 1;
            As[nxt][akc + 0][ar] = pa0.x; As[nxt][akc + 1][ar] = pa0.y;
            As[nxt][akc + 2][ar] = pa0.z; As[nxt][akc + 3][ar] = pa0.w;
            As[nxt][akc + 0][ar + 64] = pa1.x; As[nxt][akc + 1][ar + 64] = pa1.y;
            As[nxt][akc + 2][ar + 64] = pa1.z; As[nxt][akc + 3][ar + 64] = pa1.w;
            *(float4*)&Bs[nxt][bk_][bn4]      = pbg;
            *(float4*)&Bs[nxt][bk_][bn4 + 64] = pbu;
            __syncthreads();
        }
    }

#pragma unroll
    for (int i = 0; i < 8; i++) {
        int pos = row0 + (i < 4 ? ty * 4 + i : 64 + ty * 4 + (i - 4));
        if (!isExp || pos < nrows) {
            float* o = isExp ? (g_h + ((size_t)e * TT + pos) * HH + colg0 + tx * 4)
                             : (g_hs + (size_t)pos * HSD + colg0 + tx * 4);
            float4 v;
            v.x = cu[i][0] * silu(cg[i][0]);
            v.y = cu[i][1] * silu(cg[i][1]);
            v.z = cu[i][2] * silu(cg[i][2]);
            v.w = cu[i][3] * silu(cg[i][3]);
            *(float4*)o = v;
        }
    }
}

// ===================== merged down GEMM (expert + shared roles) ====================
// block: 128 rows x 128 cols; both roles atomicAdd into pre-zeroed out
__global__ void __launch_bounds__(256, 2) down_merged_kernel(
    const float* __restrict__ w_down,
    const float* __restrict__ shw_down,
    float* __restrict__ out)
{
    __shared__ alignas(16) float As[2][BK][SSTR];
    __shared__ alignas(16) float Bs[2][BK][SSTR];

    int bid = blockIdx.x;
    bool isExp = (bid < DEXP_BLKS);

    int e = 0, row0, col0, nrows, Kdim;
    const float* wd;
    const float* abase;
    if (isExp) {
        e = bid / (DNX * DNY);
        int rem = bid % (DNX * DNY);
        row0 = (rem / DNX) * 128;
        col0 = (rem % DNX) * 128;
        nrows = g_cnt[e];
        if (row0 >= nrows) return;
        wd = w_down + (size_t)e * HH * DD;
        Kdim = HH;
        abase = g_h + ((size_t)e * TT) * HH;
    } else {
        int sid = bid - DEXP_BLKS;
        row0 = (sid / DNX) * 128;
        col0 = (sid % DNX) * 128;
        nrows = TT;
        wd = shw_down;
        Kdim = HSD;
        abase = g_hs;
    }

    int tid = threadIdx.x;
    int tx = tid & 15, ty = tid >> 4;
    int ar  = tid >> 2;
    int akc = (tid & 3) << 2;
    int bk0 = tid >> 5;
    int bn4 = (tid & 31) << 2;

    const float* arow0 = abase + (size_t)(row0 + ar) * Kdim;
    const float* arow1 = abase + (size_t)(row0 + ar + 64) * Kdim;

    float c[8][8];
#pragma unroll
    for (int i = 0; i < 8; i++)
#pragma unroll
        for (int j = 0; j < 8; j++) c[i][j] = 0.f;

    const int NS = Kdim / BK;

    {
        float4 v0 = *(const float4*)(arow0 + akc);
        float4 v1 = *(const float4*)(arow1 + akc);
        As[0][akc + 0][ar] = v0.x; As[0][akc + 1][ar] = v0.y;
        As[0][akc + 2][ar] = v0.z; As[0][akc + 3][ar] = v0.w;
        As[0][akc + 0][ar + 64] = v1.x; As[0][akc + 1][ar + 64] = v1.y;
        As[0][akc + 2][ar + 64] = v1.z; As[0][akc + 3][ar + 64] = v1.w;
        *(float4*)&Bs[0][bk0][bn4]     = *(const float4*)(wd + (size_t)bk0 * DD + col0 + bn4);
        *(float4*)&Bs[0][bk0 + 8][bn4] = *(const float4*)(wd + (size_t)(bk0 + 8) * DD + col0 + bn4);
    }
    __syncthreads();

    for (int s = 0; s < NS; s++) {
        int cur = s & 1;
        float4 pa0, pa1, pb0, pb1;
        if (s + 1 < NS) {
            int k1 = (s + 1) * BK;
            pa0 = *(const float4*)(arow0 + k1 + akc);
            pa1 = *(const float4*)(arow1 + k1 + akc);
            pb0 = *(const float4*)(wd + (size_t)(k1 + bk0) * DD + col0 + bn4);
            pb1 = *(const float4*)(wd + (size_t)(k1 + bk0 + 8) * DD + col0 + bn4);
        }
        const float (*Ac)[SSTR] = As[cur];
        const float (*Bc)[SSTR] = Bs[cur];
#pragma unroll
        for (int kk = 0; kk < BK; kk++) {
            float4 a0 = *(const float4*)&Ac[kk][ty * 4];
            float4 a1 = *(const float4*)&Ac[kk][ty * 4 + 64];
            float4 b0 = *(const float4*)&Bc[kk][tx * 4];
            float4 b1 = *(const float4*)&Bc[kk][tx * 4 + 64];
            float av[8] = { a0.x, a0.y, a0.z, a0.w, a1.x, a1.y, a1.z, a1.w };
            float bv[8] = { b0.x, b0.y, b0.z, b0.w, b1.x, b1.y, b1.z, b1.w };
#pragma unroll
            for (int i = 0; i < 8; i++)
#pragma unroll
                for (int j = 0; j < 8; j++)
                    c[i][j] = fmaf(av[i], bv[j], c[i][j]);
        }
        if (s + 1 < NS) {
            int nxt = cur ^ 1;
            As[nxt][akc + 0][ar] = pa0.x; As[nxt][akc + 1][ar] = pa0.y;
            As[nxt][akc + 2][ar] = pa0.z; As[nxt][akc + 3][ar] = pa0.w;
            As[nxt][akc + 0][ar + 64] = pa1.x; As[nxt][akc + 1][ar + 64] = pa1.y;
            As[nxt][akc + 2][ar + 64] = pa1.z; As[nxt][akc + 3][ar + 64] = pa1.w;
            *(float4*)&Bs[nxt][bk0][bn4]     = pb0;
            *(float4*)&Bs[nxt][bk0 + 8][bn4] = pb1;
            __syncthreads();
        }
    }

#pragma unroll
    for (int i = 0; i < 8; i++) {
        int pos = row0 + (i < 4 ? ty * 4 + i : 64 + ty * 4 + (i - 4));
        if (isExp) {
            if (pos < nrows) {
                int tok = g_perm[e * TT + pos];
                float cw = g_cw[e * TT + pos];
                float* op = out + (size_t)tok * DD + col0;
#pragma unroll
                for (int j = 0; j < 4; j++) {
                    atomicAdd(op + tx * 4 + j,      cw * c[i][j]);
                    atomicAdd(op + 64 + tx * 4 + j, cw * c[i][j + 4]);
                }
            }
        } else {
            float sg = g_sgate[pos];
            float* op = out + (size_t)pos * DD + col0;
#pragma unroll
            for (int j = 0; j < 4; j++) {
                atomicAdd(op + tx * 4 + j,      sg * c[i][j]);
                atomicAdd(op + 64 + tx * 4 + j, sg * c[i][j + 4]);
            }
        }
    }
}

// ---------------- launch ----------------------------------------------------------
extern "C" void kernel_launch(void* const* d_in, const int* in_sizes, int n_in,
                              void* d_out, int out_size)
{
    const float* x        = (const float*)d_in[0];
    const float* gate_w   = (const float*)d_in[1];
    const float* w_gate   = (const float*)d_in[2];
    const float* w_up     = (const float*)d_in[3];
    const float* w_down   = (const float*)d_in[4];
    const float* shgate_w = (const float*)d_in[5];
    const float* shw_gate = (const float*)d_in[6];
    const float* shw_up   = (const float*)d_in[7];
    const float* shw_down = (const float*)d_in[8];
    float* out = (float*)d_out;

    cudaMemsetAsync(out, 0, (size_t)out_size * sizeof(float));
    zero_cnt_kernel<<<1, 32>>>();
    router_kernel<<<TT, 256>>>(x, gate_w, shgate_w);
    gateup_merged_kernel<<<GU_BLKS, 256>>>(x, w_gate, w_up, shw_gate, shw_up);
    down_merged_kernel<<<DN_BLKS, 256>>>(w_down, shw_down, out);
}

// round 16
// speedup vs baseline: 1.0863x; 1.0171x over previous
#include <cuda_runtime.h>
#include <cuda_pipeline.h>
#include <cstdint>

#define TT 2048
#define DD 2048
#define EE 8
#define HH 1408
#define HSD 2816

#define BK 16
#define SSTR 132   // smem row stride (floats) for [BK][128] tiles

// merged gateup grid decomposition
#define EXPX 22            // HH/64
#define EXPY 16            // TT/128
#define EXP_BLKS (EXPX * EXPY * EE)   // 2816
#define SHX 44             // HSD/64
#define SH_BLKS (SHX * 16)            // 704
#define GU_BLKS (EXP_BLKS + SH_BLKS)  // 3520

// merged down grid decomposition (block = 128 rows x 128 cols)
#define DNX 16             // DD/128
#define DNY 16             // TT/128
#define DEXP_BLKS (DNX * DNY * EE)    // 2048
#define DSH_BLKS (DNX * DNY)          // 256
#define DN_BLKS (DEXP_BLKS + DSH_BLKS)

__device__ __forceinline__ float silu(float g) { return g / (1.f + __expf(-g)); }

// ---------------- scratch ------------------------------------------------------
__device__ int   g_cnt[EE];
__device__ int   g_perm[EE * TT];
__device__ float g_cw[EE * TT];
__device__ float g_sgate[TT];
__device__ float g_h[(size_t)EE * TT * HH];
__device__ float g_hs[(size_t)TT * HSD];

// ---------------- kernel 0 -------------------------------------------------------
__global__ void zero_cnt_kernel() {
    if (threadIdx.x < EE) g_cnt[threadIdx.x] = 0;
}

// ---------------- kernel 1: router -----------------------------------------------
__global__ void __launch_bounds__(256) router_kernel(
    const float* __restrict__ x,
    const float* __restrict__ gate_w,
    const float* __restrict__ shgate_w)
{
    int t = blockIdx.x;
    const float* xr = x + (size_t)t * DD;
    float acc[9];
#pragma unroll
    for (int v = 0; v < 9; v++) acc[v] = 0.f;
    for (int j = threadIdx.x; j < DD; j += 256) {
        float xv = xr[j];
#pragma unroll
        for (int e = 0; e < EE; e++) acc[e] = fmaf(xv, gate_w[e * DD + j], acc[e]);
        acc[8] = fmaf(xv, shgate_w[j], acc[8]);
    }
#pragma unroll
    for (int o = 16; o > 0; o >>= 1) {
#pragma unroll
        for (int v = 0; v < 9; v++) acc[v] += __shfl_down_sync(0xffffffffu, acc[v], o);
    }
    __shared__ float sred[9][8];
    int lane = threadIdx.x & 31, wid = threadIdx.x >> 5;
    if (lane == 0) {
#pragma unroll
        for (int v = 0; v < 9; v++) sred[v][wid] = acc[v];
    }
    __syncthreads();
    if (threadIdx.x == 0) {
        float l[9];
#pragma unroll
        for (int v = 0; v < 9; v++) {
            float s = 0.f;
#pragma unroll
            for (int w = 0; w < 8; w++) s += sred[v][w];
            l[v] = s;
        }
        float m = l[0];
#pragma unroll
        for (int e = 1; e < EE; e++) m = fmaxf(m, l[e]);
        float p[EE];
#pragma unroll
        for (int e = 0; e < EE; e++) p[e] = expf(l[e] - m);
        int i0 = 0;
#pragma unroll
        for (int e = 1; e < EE; e++) if (p[e] > p[i0]) i0 = e;
        int i1 = (i0 == 0) ? 1 : 0;
#pragma unroll
        for (int e = 0; e < EE; e++) if (e != i0 && p[e] > p[i1]) i1 = e;
        float inv = 1.f / (p[i0] + p[i1]);
        int q0 = atomicAdd(&g_cnt[i0], 1);
        g_perm[i0 * TT + q0] = t;
        g_cw[i0 * TT + q0]   = p[i0] * inv;
        int q1 = atomicAdd(&g_cnt[i1], 1);
        g_perm[i1 * TT + q1] = t;
        g_cw[i1 * TT + q1]   = p[i1] * inv;
        g_sgate[t] = 1.f / (1.f + expf(-l[8]));
    }
}

// ===================== merged gate/up GEMM (cp.async B, 3-stage) ===================
__global__ void __launch_bounds__(256, 2) gateup_merged_kernel(
    const float* __restrict__ x,
    const float* __restrict__ w_gate,
    const float* __restrict__ w_up,
    const float* __restrict__ shw_gate,
    const float* __restrict__ shw_up)
{
    __shared__ alignas(16) float As[2][BK][SSTR];
    __shared__ alignas(16) float Bs[3][BK][SSTR];

    int bid = blockIdx.x;
    bool isExp = (bid < EXP_BLKS);

    int e = 0, row0, colg0, nrows, Ndim;
    const float *wg, *wu;
    if (isExp) {
        e = bid / (EXPX * EXPY);
        int rem = bid % (EXPX * EXPY);
        row0 = (rem / EXPX) * 128;
        colg0 = (rem % EXPX) * 64;
        nrows = g_cnt[e];
        if (row0 >= nrows) return;
        wg = w_gate + (size_t)e * DD * HH;
        wu = w_up   + (size_t)e * DD * HH;
        Ndim = HH;
    } else {
        int sid = bid - EXP_BLKS;
        row0 = (sid / SHX) * 128;
        colg0 = (sid % SHX) * 64;
        nrows = TT;
        wg = shw_gate; wu = shw_up;
        Ndim = HSD;
    }

    int tid = threadIdx.x;
    int tx = tid & 15, ty = tid >> 4;
    int bk_ = tid >> 4;
    int bn4 = (tid & 15) << 2;
    int ar  = tid >> 2;
    int akc = (tid & 3) << 2;

    const float* arow0;
    const float* arow1;
    {
        int pos0 = row0 + ar, pos1 = row0 + ar + 64;
        if (isExp) {
            int tok0 = (pos0 < nrows) ? g_perm[e * TT + pos0] : g_perm[e * TT];
            int tok1 = (pos1 < nrows) ? g_perm[e * TT + pos1] : g_perm[e * TT];
            arow0 = x + (size_t)tok0 * DD;
            arow1 = x + (size_t)tok1 * DD;
        } else {
            arow0 = x + (size_t)pos0 * DD;
            arow1 = x + (size_t)pos1 * DD;
        }
    }

    // per-thread B source/dst offsets
    const float* wgp = wg + (size_t)bk_ * Ndim + colg0 + bn4;
    const float* wup = wu + (size_t)bk_ * Ndim + colg0 + bn4;
    const size_t bstep = (size_t)BK * Ndim;

    float cg[8][4], cu[8][4];
#pragma unroll
    for (int i = 0; i < 8; i++)
#pragma unroll
        for (int j = 0; j < 4; j++) { cg[i][j] = 0.f; cu[i][j] = 0.f; }

    const int NS = DD / BK;

    // prologue: A slab0 -> As[0]; cp.async B slab0,1
    {
        float4 v0 = *(const float4*)(arow0 + akc);
        float4 v1 = *(const float4*)(arow1 + akc);
        As[0][akc + 0][ar] = v0.x; As[0][akc + 1][ar] = v0.y;
        As[0][akc + 2][ar] = v0.z; As[0][akc + 3][ar] = v0.w;
        As[0][akc + 0][ar + 64] = v1.x; As[0][akc + 1][ar + 64] = v1.y;
        As[0][akc + 2][ar + 64] = v1.z; As[0][akc + 3][ar + 64] = v1.w;
        __pipeline_memcpy_async(&Bs[0][bk_][bn4],      wgp, 16);
        __pipeline_memcpy_async(&Bs[0][bk_][bn4 + 64], wup, 16);
        __pipeline_commit();
        __pipeline_memcpy_async(&Bs[1][bk_][bn4],      wgp + bstep, 16);
        __pipeline_memcpy_async(&Bs[1][bk_][bn4 + 64], wup + bstep, 16);
        __pipeline_commit();
    }
    // A prefetch for slab 1
    float4 pa0 = *(const float4*)(arow0 + BK + akc);
    float4 pa1 = *(const float4*)(arow1 + BK + akc);

    for (int s = 0; s < NS; s++) {
        __pipeline_wait_prior((s + 1 < NS) ? 1 : 0);
        __syncthreads();
        if (s + 2 < NS) {
            size_t off = (size_t)(s + 2) * bstep;
            float* bd = &Bs[(s + 2) % 3][bk_][bn4];
            __pipeline_memcpy_async(bd,      wgp + off, 16);
            __pipeline_memcpy_async(bd + 64, wup + off, 16);
            __pipeline_commit();
        }
        if (s + 1 < NS) {
            int nb = (s + 1) & 1;
            As[nb][akc + 0][ar] = pa0.x; As[nb][akc + 1][ar] = pa0.y;
            As[nb][akc + 2][ar] = pa0.z; As[nb][akc + 3][ar] = pa0.w;
            As[nb][akc + 0][ar + 64] = pa1.x; As[nb][akc + 1][ar + 64] = pa1.y;
            As[nb][akc + 2][ar + 64] = pa1.z; As[nb][akc + 3][ar + 64] = pa1.w;
        }
        if (s + 2 < NS) {
            int k2 = (s + 2) * BK;
            pa0 = *(const float4*)(arow0 + k2 + akc);
            pa1 = *(const float4*)(arow1 + k2 + akc);
        }
        const float (*Ac)[SSTR] = As[s & 1];
        const float (*Bc)[SSTR] = Bs[s % 3];
#pragma unroll
        for (int kk = 0; kk < BK; kk++) {
            float4 a0 = *(const float4*)&Ac[kk][ty * 4];
            float4 a1 = *(const float4*)&Ac[kk][ty * 4 + 64];
            float4 bg = *(const float4*)&Bc[kk][tx * 4];
            float4 bu = *(const float4*)&Bc[kk][tx * 4 + 64];
            float av[8] = { a0.x, a0.y, a0.z, a0.w, a1.x, a1.y, a1.z, a1.w };
            float bgv[4] = { bg.x, bg.y, bg.z, bg.w };
            float buv[4] = { bu.x, bu.y, bu.z, bu.w };
#pragma unroll
            for (int i = 0; i < 8; i++)
#pragma unroll
                for (int j = 0; j < 4; j++) {
                    cg[i][j] = fmaf(av[i], bgv[j], cg[i][j]);
                    cu[i][j] = fmaf(av[i], buv[j], cu[i][j]);
                }
        }
    }

#pragma unroll
    for (int i = 0; i < 8; i++) {
        int pos = row0 + (i < 4 ? ty * 4 + i : 64 + ty * 4 + (i - 4));
        if (!isExp || pos < nrows) {
            float* o = isExp ? (g_h + ((size_t)e * TT + pos) * HH + colg0 + tx * 4)
                             : (g_hs + (size_t)pos * HSD + colg0 + tx * 4);
            float4 v;
            v.x = cu[i][0] * silu(cg[i][0]);
            v.y = cu[i][1] * silu(cg[i][1]);
            v.z = cu[i][2] * silu(cg[i][2]);
            v.w = cu[i][3] * silu(cg[i][3]);
            *(float4*)o = v;
        }
    }
}

// ===================== merged down GEMM (cp.async B, 3-stage) ======================
__global__ void __launch_bounds__(256, 2) down_merged_kernel(
    const float* __restrict__ w_down,
    const float* __restrict__ shw_down,
    float* __restrict__ out)
{
    __shared__ alignas(16) float As[2][BK][SSTR];
    __shared__ alignas(16) float Bs[3][BK][SSTR];

    int bid = blockIdx.x;
    bool isExp = (bid < DEXP_BLKS);

    int e = 0, row0, col0, nrows, Kdim;
    const float* wd;
    const float* abase;
    if (isExp) {
        e = bid / (DNX * DNY);
        int rem = bid % (DNX * DNY);
        row0 = (rem / DNX) * 128;
        col0 = (rem % DNX) * 128;
        nrows = g_cnt[e];
        if (row0 >= nrows) return;
        wd = w_down + (size_t)e * HH * DD;
        Kdim = HH;
        abase = g_h + ((size_t)e * TT) * HH;
    } else {
        int sid = bid - DEXP_BLKS;
        row0 = (sid / DNX) * 128;
        col0 = (sid % DNX) * 128;
        nrows = TT;
        wd = shw_down;
        Kdim = HSD;
        abase = g_hs;
    }

    int tid = threadIdx.x;
    int tx = tid & 15, ty = tid >> 4;
    int ar  = tid >> 2;
    int akc = (tid & 3) << 2;
    int bk0 = tid >> 5;
    int bn4 = (tid & 31) << 2;

    const float* arow0 = abase + (size_t)(row0 + ar) * Kdim;
    const float* arow1 = abase + (size_t)(row0 + ar + 64) * Kdim;
    const float* wdp0 = wd + (size_t)bk0 * DD + col0 + bn4;
    const float* wdp1 = wd + (size_t)(bk0 + 8) * DD + col0 + bn4;
    const size_t bstep = (size_t)BK * DD;

    float c[8][8];
#pragma unroll
    for (int i = 0; i < 8; i++)
#pragma unroll
        for (int j = 0; j < 8; j++) c[i][j] = 0.f;

    const int NS = Kdim / BK;

    {
        float4 v0 = *(const float4*)(arow0 + akc);
        float4 v1 = *(const float4*)(arow1 + akc);
        As[0][akc + 0][ar] = v0.x; As[0][akc + 1][ar] = v0.y;
        As[0][akc + 2][ar] = v0.z; As[0][akc + 3][ar] = v0.w;
        As[0][akc + 0][ar + 64] = v1.x; As[0][akc + 1][ar + 64] = v1.y;
        As[0][akc + 2][ar + 64] = v1.z; As[0][akc + 3][ar + 64] = v1.w;
        __pipeline_memcpy_async(&Bs[0][bk0][bn4],     wdp0, 16);
        __pipeline_memcpy_async(&Bs[0][bk0 + 8][bn4], wdp1, 16);
        __pipeline_commit();
        __pipeline_memcpy_async(&Bs[1][bk0][bn4],     wdp0 + bstep, 16);
        __pipeline_memcpy_async(&Bs[1][bk0 + 8][bn4], wdp1 + bstep, 16);
        __pipeline_commit();
    }
    float4 pa0 = *(const float4*)(arow0 + BK + akc);
    float4 pa1 = *(const float4*)(arow1 + BK + akc);

    for (int s = 0; s < NS; s++) {
        __pipeline_wait_prior((s + 1 < NS) ? 1 : 0);
        __syncthreads();
        if (s + 2 < NS) {
            size_t off = (size_t)(s + 2) * bstep;
            int rb = (s + 2) % 3;
            __pipeline_memcpy_async(&Bs[rb][bk0][bn4],     wdp0 + off, 16);
            __pipeline_memcpy_async(&Bs[rb][bk0 + 8][bn4], wdp1 + off, 16);
            __pipeline_commit();
        }
        if (s + 1 < NS) {
            int nb = (s + 1) & 1;
            As[nb][akc + 0][ar] = pa0.x; As[nb][akc + 1][ar] = pa0.y;
            As[nb][akc + 2][ar] = pa0.z; As[nb][akc + 3][ar] = pa0.w;
            As[nb][akc + 0][ar + 64] = pa1.x; As[nb][akc + 1][ar + 64] = pa1.y;
            As[nb][akc + 2][ar + 64] = pa1.z; As[nb][akc + 3][ar + 64] = pa1.w;
        }
        if (s + 2 < NS) {
            int k2 = (s + 2) * BK;
            pa0 = *(const float4*)(arow0 + k2 + akc);
            pa1 = *(const float4*)(arow1 + k2 + akc);
        }
        const float (*Ac)[SSTR] = As[s & 1];
        const float (*Bc)[SSTR] = Bs[s % 3];
#pragma unroll
        for (int kk = 0; kk < BK; kk++) {
            float4 a0 = *(const float4*)&Ac[kk][ty * 4];
            float4 a1 = *(const float4*)&Ac[kk][ty * 4 + 64];
            float4 b0 = *(const float4*)&Bc[kk][tx * 4];
            float4 b1 = *(const float4*)&Bc[kk][tx * 4 + 64];
            float av[8] = { a0.x, a0.y, a0.z, a0.w, a1.x, a1.y, a1.z, a1.w };
            float bv[8] = { b0.x, b0.y, b0.z, b0.w, b1.x, b1.y, b1.z, b1.w };
#pragma unroll
            for (int i = 0; i < 8; i++)
#pragma unroll
                for (int j = 0; j < 8; j++)
                    c[i][j] = fmaf(av[i], bv[j], c[i][j]);
        }
    }

#pragma unroll
    for (int i = 0; i < 8; i++) {
        int pos = row0 + (i < 4 ? ty * 4 + i : 64 + ty * 4 + (i - 4));
        if (isExp) {
            if (pos < nrows) {
                int tok = g_perm[e * TT + pos];
                float cw = g_cw[e * TT + pos];
                float* op = out + (size_t)tok * DD + col0;
#pragma unroll
                for (int j = 0; j < 4; j++) {
                    atomicAdd(op + tx * 4 + j,      cw * c[i][j]);
                    atomicAdd(op + 64 + tx * 4 + j, cw * c[i][j + 4]);
                }
            }
        } else {
            float sg = g_sgate[pos];
            float* op = out + (size_t)pos * DD + col0;
#pragma unroll
            for (int j = 0; j < 4; j++) {
                atomicAdd(op + tx * 4 + j,      sg * c[i][j]);
                atomicAdd(op + 64 + tx * 4 + j, sg * c[i][j + 4]);
            }
        }
    }
}

// ---------------- launch ----------------------------------------------------------
extern "C" void kernel_launch(void* const* d_in, const int* in_sizes, int n_in,
                              void* d_out, int out_size)
{
    const float* x        = (const float*)d_in[0];
    const float* gate_w   = (const float*)d_in[1];
    const float* w_gate   = (const float*)d_in[2];
    const float* w_up     = (const float*)d_in[3];
    const float* w_down   = (const float*)d_in[4];
    const float* shgate_w = (const float*)d_in[5];
    const float* shw_gate = (const float*)d_in[6];
    const float* shw_up   = (const float*)d_in[7];
    const float* shw_down = (const float*)d_in[8];
    float* out = (float*)d_out;

    cudaMemsetAsync(out, 0, (size_t)out_size * sizeof(float));
    zero_cnt_kernel<<<1, 32>>>();
    router_kernel<<<TT, 256>>>(x, gate_w, shgate_w);
    gateup_merged_kernel<<<GU_BLKS, 256>>>(x, w_gate, w_up, shw_gate, shw_up);
    down_merged_kernel<<<DN_BLKS, 256>>>(w_down, shw_down, out);
}

// round 17
// speedup vs baseline: 1.1690x; 1.0761x over previous
#include <cuda_runtime.h>
#include <cuda_pipeline.h>
#include <cstdint>

#define TT 2048
#define DD 2048
#define EE 8
#define HH 1408
#define HSD 2816

#define SSTR 132   // smem row stride (floats)

// merged gateup grid decomposition
#define EXPX 22
#define EXPY 16
#define EXP_BLKS (EXPX * EXPY * EE)   // 2816
#define SHX 44
#define SH_BLKS (SHX * 16)            // 704
#define GU_BLKS (EXP_BLKS + SH_BLKS)

// merged down grid decomposition
#define DNX 16
#define DNY 16
#define DEXP_BLKS (DNX * DNY * EE)    // 2048
#define DN_BLKS (DEXP_BLKS + DNX * DNY)

// dynamic smem: As ring 4*16*SSTR + Bs ring 2*32*SSTR  (floats)
#define A_FLOATS (4 * 16 * SSTR)
#define B_FLOATS (2 * 32 * SSTR)
#define DYN_SMEM ((A_FLOATS + B_FLOATS) * 4)

__device__ __forceinline__ float silu(float g) { return g / (1.f + __expf(-g)); }

// ---------------- scratch ------------------------------------------------------
__device__ int   g_cnt[EE];
__device__ int   g_perm[EE * TT];
__device__ float g_cw[EE * TT];
__device__ float g_sgate[TT];
__device__ float g_h[(size_t)EE * TT * HH];
__device__ float g_hs[(size_t)TT * HSD];

// ---------------- kernel 0 -------------------------------------------------------
__global__ void zero_cnt_kernel() {
    if (threadIdx.x < EE) g_cnt[threadIdx.x] = 0;
}

// ---------------- kernel 1: router -----------------------------------------------
__global__ void __launch_bounds__(256) router_kernel(
    const float* __restrict__ x,
    const float* __restrict__ gate_w,
    const float* __restrict__ shgate_w)
{
    int t = blockIdx.x;
    const float* xr = x + (size_t)t * DD;
    float acc[9];
#pragma unroll
    for (int v = 0; v < 9; v++) acc[v] = 0.f;
    for (int j = threadIdx.x; j < DD; j += 256) {
        float xv = xr[j];
#pragma unroll
        for (int e = 0; e < EE; e++) acc[e] = fmaf(xv, gate_w[e * DD + j], acc[e]);
        acc[8] = fmaf(xv, shgate_w[j], acc[8]);
    }
#pragma unroll
    for (int o = 16; o > 0; o >>= 1) {
#pragma unroll
        for (int v = 0; v < 9; v++) acc[v] += __shfl_down_sync(0xffffffffu, acc[v], o);
    }
    __shared__ float sred[9][8];
    int lane = threadIdx.x & 31, wid = threadIdx.x >> 5;
    if (lane == 0) {
#pragma unroll
        for (int v = 0; v < 9; v++) sred[v][wid] = acc[v];
    }
    __syncthreads();
    if (threadIdx.x == 0) {
        float l[9];
#pragma unroll
        for (int v = 0; v < 9; v++) {
            float s = 0.f;
#pragma unroll
            for (int w = 0; w < 8; w++) s += sred[v][w];
            l[v] = s;
        }
        float m = l[0];
#pragma unroll
        for (int e = 1; e < EE; e++) m = fmaxf(m, l[e]);
        float p[EE];
#pragma unroll
        for (int e = 0; e < EE; e++) p[e] = expf(l[e] - m);
        int i0 = 0;
#pragma unroll
        for (int e = 1; e < EE; e++) if (p[e] > p[i0]) i0 = e;
        int i1 = (i0 == 0) ? 1 : 0;
#pragma unroll
        for (int e = 0; e < EE; e++) if (e != i0 && p[e] > p[i1]) i1 = e;
        float inv = 1.f / (p[i0] + p[i1]);
        int q0 = atomicAdd(&g_cnt[i0], 1);
        g_perm[i0 * TT + q0] = t;
        g_cw[i0 * TT + q0]   = p[i0] * inv;
        int q1 = atomicAdd(&g_cnt[i1], 1);
        g_perm[i1 * TT + q1] = t;
        g_cw[i1 * TT + q1]   = p[i1] * inv;
        g_sgate[t] = 1.f / (1.f + expf(-l[8]));
    }
}

// A half-store helper: 2 float4 (k = akc..akc+3, akc+4..akc+7) into As[slot][k][ar]
#define ASTORE(slot, v0, v1)                                                \
    do {                                                                    \
        float* base = &Adyn[(slot) * (16 * SSTR)];                          \
        base[(akc + 0) * SSTR + ar] = (v0).x;                               \
        base[(akc + 1) * SSTR + ar] = (v0).y;                               \
        base[(akc + 2) * SSTR + ar] = (v0).z;                               \
        base[(akc + 3) * SSTR + ar] = (v0).w;                               \
        base[(akc + 4) * SSTR + ar] = (v1).x;                               \
        base[(akc + 5) * SSTR + ar] = (v1).y;                               \
        base[(akc + 6) * SSTR + ar] = (v1).z;                               \
        base[(akc + 7) * SSTR + ar] = (v1).w;                               \
    } while (0)

// ===================== merged gate/up GEMM (BK=32, rings) ==========================
__global__ void __launch_bounds__(256, 2) gateup_merged_kernel(
    const float* __restrict__ x,
    const float* __restrict__ w_gate,
    const float* __restrict__ w_up,
    const float* __restrict__ shw_gate,
    const float* __restrict__ shw_up)
{
    extern __shared__ float Adyn[];             // [4][16][SSTR]
    float* Bdyn = Adyn + A_FLOATS;              // [2][32][SSTR]

    int bid = blockIdx.x;
    bool isExp = (bid < EXP_BLKS);

    int e = 0, row0, colg0, nrows, Ndim;
    const float *wg, *wu;
    if (isExp) {
        e = bid / (EXPX * EXPY);
        int rem = bid % (EXPX * EXPY);
        row0 = (rem / EXPX) * 128;
        colg0 = (rem % EXPX) * 64;
        nrows = g_cnt[e];
        if (row0 >= nrows) return;
        wg = w_gate + (size_t)e * DD * HH;
        wu = w_up   + (size_t)e * DD * HH;
        Ndim = HH;
    } else {
        int sid = bid - EXP_BLKS;
        row0 = (sid / SHX) * 128;
        colg0 = (sid % SHX) * 64;
        nrows = TT;
        wg = shw_gate; wu = shw_up;
        Ndim = HSD;
    }

    int tid = threadIdx.x;
    int tx = tid & 15, ty = tid >> 4;
    int ar  = tid >> 1;          // A loader row 0..127
    int akc = (tid & 1) << 3;    // A loader k base within half: 0 or 8
    int bk_ = tid >> 4;          // B loader k row 0..15 (plus +16)
    int bn4 = (tid & 15) << 2;

    const float* arow;
    {
        int pos = row0 + ar;
        if (isExp) {
            int tok = (pos < nrows) ? g_perm[e * TT + pos] : g_perm[e * TT];
            arow = x + (size_t)tok * DD;
        } else {
            arow = x + (size_t)pos * DD;
        }
    }
    const float* wgp = wg + (size_t)bk_ * Ndim + colg0 + bn4;
    const float* wup = wu + (size_t)bk_ * Ndim + colg0 + bn4;
    const size_t brow16 = (size_t)16 * Ndim;
    const size_t bstep = (size_t)32 * Ndim;

    float cg[8][4], cu[8][4];
#pragma unroll
    for (int i = 0; i < 8; i++)
#pragma unroll
        for (int j = 0; j < 4; j++) { cg[i][j] = 0.f; cu[i][j] = 0.f; }

    const int NS = DD / 32;   // 64

    // prologue: A slab0 h0->slot0, h1->slot1; pa <- slab1 h0; B slab0 -> buf0
    float4 pa0, pa1;
    {
        float4 v0 = *(const float4*)(arow + akc);
        float4 v1 = *(const float4*)(arow + akc + 4);
        ASTORE(0, v0, v1);
        v0 = *(const float4*)(arow + 16 + akc);
        v1 = *(const float4*)(arow + 16 + akc + 4);
        ASTORE(1, v0, v1);
        pa0 = *(const float4*)(arow + 32 + akc);
        pa1 = *(const float4*)(arow + 32 + akc + 4);
        float* bb = Bdyn + (size_t)bk_ * SSTR + bn4;
        __pipeline_memcpy_async(bb,                    wgp, 16);
        __pipeline_memcpy_async(bb + 16 * SSTR,        wgp + brow16, 16);
        __pipeline_memcpy_async(bb + 64,               wup, 16);
        __pipeline_memcpy_async(bb + 16 * SSTR + 64,   wup + brow16, 16);
        __pipeline_commit();
    }

    for (int s = 0; s < NS; s++) {
        __pipeline_wait_prior(0);
        __syncthreads();
        if (s + 1 < NS) {
            size_t off = (size_t)(s + 1) * bstep;
            float* bb = Bdyn + (size_t)((s + 1) & 1) * (32 * SSTR)
                      + (size_t)bk_ * SSTR + bn4;
            __pipeline_memcpy_async(bb,                  wgp + off, 16);
            __pipeline_memcpy_async(bb + 16 * SSTR,      wgp + off + brow16, 16);
            __pipeline_memcpy_async(bb + 64,             wup + off, 16);
            __pipeline_memcpy_async(bb + 16 * SSTR + 64, wup + off + brow16, 16);
            __pipeline_commit();
            ASTORE((2 * s + 2) & 3, pa0, pa1);   // slab s+1 half0
            pa0 = *(const float4*)(arow + (s + 1) * 32 + 16 + akc);
            pa1 = *(const float4*)(arow + (s + 1) * 32 + 16 + akc + 4);
        }
        const float* Ac0 = &Adyn[((2 * s) & 3) * (16 * SSTR)];
        const float* Bc  = Bdyn + (size_t)(s & 1) * (32 * SSTR);
#pragma unroll
        for (int kk = 0; kk < 16; kk++) {
            float4 a0 = *(const float4*)(Ac0 + kk * SSTR + ty * 4);
            float4 a1 = *(const float4*)(Ac0 + kk * SSTR + ty * 4 + 64);
            float4 bg = *(const float4*)(Bc + kk * SSTR + tx * 4);
            float4 bu = *(const float4*)(Bc + kk * SSTR + tx * 4 + 64);
            float av[8] = { a0.x, a0.y, a0.z, a0.w, a1.x, a1.y, a1.z, a1.w };
            float bgv[4] = { bg.x, bg.y, bg.z, bg.w };
            float buv[4] = { bu.x, bu.y, bu.z, bu.w };
#pragma unroll
            for (int i = 0; i < 8; i++)
#pragma unroll
                for (int j = 0; j < 4; j++) {
                    cg[i][j] = fmaf(av[i], bgv[j], cg[i][j]);
                    cu[i][j] = fmaf(av[i], buv[j], cu[i][j]);
                }
        }
        if (s + 1 < NS) {
            ASTORE((2 * s + 3) & 3, pa0, pa1);   // slab s+1 half1
            if (s + 2 < NS) {
                pa0 = *(const float4*)(arow + (s + 2) * 32 + akc);
                pa1 = *(const float4*)(arow + (s + 2) * 32 + akc + 4);
            }
        }
        const float* Ac1 = &Adyn[((2 * s + 1) & 3) * (16 * SSTR)];
#pragma unroll
        for (int kk = 0; kk < 16; kk++) {
            float4 a0 = *(const float4*)(Ac1 + kk * SSTR + ty * 4);
            float4 a1 = *(const float4*)(Ac1 + kk * SSTR + ty * 4 + 64);
            float4 bg = *(const float4*)(Bc + (16 + kk) * SSTR + tx * 4);
            float4 bu = *(const float4*)(Bc + (16 + kk) * SSTR + tx * 4 + 64);
            float av[8] = { a0.x, a0.y, a0.z, a0.w, a1.x, a1.y, a1.z, a1.w };
            float bgv[4] = { bg.x, bg.y, bg.z, bg.w };
            float buv[4] = { bu.x, bu.y, bu.z, bu.w };
#pragma unroll
            for (int i = 0; i < 8; i++)
#pragma unroll
                for (int j = 0; j < 4; j++) {
                    cg[i][j] = fmaf(av[i], bgv[j], cg[i][j]);
                    cu[i][j] = fmaf(av[i], buv[j], cu[i][j]);
                }
        }
    }

#pragma unroll
    for (int i = 0; i < 8; i++) {
        int pos = row0 + (i < 4 ? ty * 4 + i : 64 + ty * 4 + (i - 4));
        if (!isExp || pos < nrows) {
            float* o = isExp ? (g_h + ((size_t)e * TT + pos) * HH + colg0 + tx * 4)
                             : (g_hs + (size_t)pos * HSD + colg0 + tx * 4);
            float4 v;
            v.x = cu[i][0] * silu(cg[i][0]);
            v.y = cu[i][1] * silu(cg[i][1]);
            v.z = cu[i][2] * silu(cg[i][2]);
            v.w = cu[i][3] * silu(cg[i][3]);
            *(float4*)o = v;
        }
    }
}

// ===================== merged down GEMM (BK=32, rings) =============================
__global__ void __launch_bounds__(256, 2) down_merged_kernel(
    const float* __restrict__ w_down,
    const float* __restrict__ shw_down,
    float* __restrict__ out)
{
    extern __shared__ float Adyn[];
    float* Bdyn = Adyn + A_FLOATS;

    int bid = blockIdx.x;
    bool isExp = (bid < DEXP_BLKS);

    int e = 0, row0, col0, nrows, Kdim;
    const float* wd;
    const float* abase;
    if (isExp) {
        e = bid / (DNX * DNY);
        int rem = bid % (DNX * DNY);
        row0 = (rem / DNX) * 128;
        col0 = (rem % DNX) * 128;
        nrows = g_cnt[e];
        if (row0 >= nrows) return;
        wd = w_down + (size_t)e * HH * DD;
        Kdim = HH;
        abase = g_h + ((size_t)e * TT) * HH;
    } else {
        int sid = bid - DEXP_BLKS;
        row0 = (sid / DNX) * 128;
        col0 = (sid % DNX) * 128;
        nrows = TT;
        wd = shw_down;
        Kdim = HSD;
        abase = g_hs;
    }

    int tid = threadIdx.x;
    int tx = tid & 15, ty = tid >> 4;
    int ar  = tid >> 1;
    int akc = (tid & 1) << 3;
    int bk0 = tid >> 5;            // 0..7; rows bk0, +8, +16, +24
    int bn4 = (tid & 31) << 2;

    const float* arow = abase + (size_t)(row0 + ar) * Kdim;
    const float* wdp = wd + (size_t)bk0 * DD + col0 + bn4;
    const size_t brow8 = (size_t)8 * DD;
    const size_t bstep = (size_t)32 * DD;

    float c[8][8];
#pragma unroll
    for (int i = 0; i < 8; i++)
#pragma unroll
        for (int j = 0; j < 8; j++) c[i][j] = 0.f;

    const int NS = Kdim / 32;

    float4 pa0, pa1;
    {
        float4 v0 = *(const float4*)(arow + akc);
        float4 v1 = *(const float4*)(arow + akc + 4);
        ASTORE(0, v0, v1);
        v0 = *(const float4*)(arow + 16 + akc);
        v1 = *(const float4*)(arow + 16 + akc + 4);
        ASTORE(1, v0, v1);
        pa0 = *(const float4*)(arow + 32 + akc);
        pa1 = *(const float4*)(arow + 32 + akc + 4);
        float* bb = Bdyn + (size_t)bk0 * SSTR + bn4;
        __pipeline_memcpy_async(bb,               wdp, 16);
        __pipeline_memcpy_async(bb + 8 * SSTR,    wdp + brow8, 16);
        __pipeline_memcpy_async(bb + 16 * SSTR,   wdp + 2 * brow8, 16);
        __pipeline_memcpy_async(bb + 24 * SSTR,   wdp + 3 * brow8, 16);
        __pipeline_commit();
    }

    for (int s = 0; s < NS; s++) {
        __pipeline_wait_prior(0);
        __syncthreads();
        if (s + 1 < NS) {
            size_t off = (size_t)(s + 1) * bstep;
            float* bb = Bdyn + (size_t)((s + 1) & 1) * (32 * SSTR)
                      + (size_t)bk0 * SSTR + bn4;
            __pipeline_memcpy_async(bb,             wdp + off, 16);
            __pipeline_memcpy_async(bb + 8 * SSTR,  wdp + off + brow8, 16);
            __pipeline_memcpy_async(bb + 16 * SSTR, wdp + off + 2 * brow8, 16);
            __pipeline_memcpy_async(bb + 24 * SSTR, wdp + off + 3 * brow8, 16);
            __pipeline_commit();
            ASTORE((2 * s + 2) & 3, pa0, pa1);
            pa0 = *(const float4*)(arow + (s + 1) * 32 + 16 + akc);
            pa1 = *(const float4*)(arow + (s + 1) * 32 + 16 + akc + 4);
        }
        const float* Ac0 = &Adyn[((2 * s) & 3) * (16 * SSTR)];
        const float* Bc  = Bdyn + (size_t)(s & 1) * (32 * SSTR);
#pragma unroll
        for (int kk = 0; kk < 16; kk++) {
            float4 a0 = *(const float4*)(Ac0 + kk * SSTR + ty * 4);
            float4 a1 = *(const float4*)(Ac0 + kk * SSTR + ty * 4 + 64);
            float4 b0 = *(const float4*)(Bc + kk * SSTR + tx * 4);
            float4 b1 = *(const float4*)(Bc + kk * SSTR + tx * 4 + 64);
            float av[8] = { a0.x, a0.y, a0.z, a0.w, a1.x, a1.y, a1.z, a1.w };
            float bv[8] = { b0.x, b0.y, b0.z, b0.w, b1.x, b1.y, b1.z, b1.w };
#pragma unroll
            for (int i = 0; i < 8; i++)
#pragma unroll
                for (int j = 0; j < 8; j++)
                    c[i][j] = fmaf(av[i], bv[j], c[i][j]);
        }
        if (s + 1 < NS) {
            ASTORE((2 * s + 3) & 3, pa0, pa1);
            if (s + 2 < NS) {
                pa0 = *(const float4*)(arow + (s + 2) * 32 + akc);
                pa1 = *(const float4*)(arow + (s + 2) * 32 + akc + 4);
            }
        }
        const float* Ac1 = &Adyn[((2 * s + 1) & 3) * (16 * SSTR)];
#pragma unroll
        for (int kk = 0; kk < 16; kk++) {
            float4 a0 = *(const float4*)(Ac1 + kk * SSTR + ty * 4);
            float4 a1 = *(const float4*)(Ac1 + kk * SSTR + ty * 4 + 64);
            float4 b0 = *(const float4*)(Bc + (16 + kk) * SSTR + tx * 4);
            float4 b1 = *(const float4*)(Bc + (16 + kk) * SSTR + tx * 4 + 64);
            float av[8] = { a0.x, a0.y, a0.z, a0.w, a1.x, a1.y, a1.z, a1.w };
            float bv[8] = { b0.x, b0.y, b0.z, b0.w, b1.x, b1.y, b1.z, b1.w };
#pragma unroll
            for (int i = 0; i < 8; i++)
#pragma unroll
                for (int j = 0; j < 8; j++)
                    c[i][j] = fmaf(av[i], bv[j], c[i][j]);
        }
    }

#pragma unroll
    for (int i = 0; i < 8; i++) {
        int pos = row0 + (i < 4 ? ty * 4 + i : 64 + ty * 4 + (i - 4));
        if (isExp) {
            if (pos < nrows) {
                int tok = g_perm[e * TT + pos];
                float cw = g_cw[e * TT + pos];
                float* op = out + (size_t)tok * DD + col0;
#pragma unroll
                for (int j = 0; j < 4; j++) {
                    atomicAdd(op + tx * 4 + j,      cw * c[i][j]);
                    atomicAdd(op + 64 + tx * 4 + j, cw * c[i][j + 4]);
                }
            }
        } else {
            float sg = g_sgate[pos];
            float* op = out + (size_t)pos * DD + col0;
#pragma unroll
            for (int j = 0; j < 4; j++) {
                atomicAdd(op + tx * 4 + j,      sg * c[i][j]);
                atomicAdd(op + 64 + tx * 4 + j, sg * c[i][j + 4]);
            }
        }
    }
}

// ---------------- launch ----------------------------------------------------------
extern "C" void kernel_launch(void* const* d_in, const int* in_sizes, int n_in,
                              void* d_out, int out_size)
{
    const float* x        = (const float*)d_in[0];
    const float* gate_w   = (const float*)d_in[1];
    const float* w_gate   = (const float*)d_in[2];
    const float* w_up     = (const float*)d_in[3];
    const float* w_down   = (const float*)d_in[4];
    const float* shgate_w = (const float*)d_in[5];
    const float* shw_gate = (const float*)d_in[6];
    const float* shw_up   = (const float*)d_in[7];
    const float* shw_down = (const float*)d_in[8];
    float* out = (float*)d_out;

    static bool attr_done = false;
    if (!attr_done) {
        cudaFuncSetAttribute(gateup_merged_kernel,
                             cudaFuncAttributeMaxDynamicSharedMemorySize, DYN_SMEM);
        cudaFuncSetAttribute(down_merged_kernel,
                             cudaFuncAttributeMaxDynamicSharedMemorySize, DYN_SMEM);
        attr_done = true;
    }

    cudaMemsetAsync(out, 0, (size_t)out_size * sizeof(float));
    zero_cnt_kernel<<<1, 32>>>();
    router_kernel<<<TT, 256>>>(x, gate_w, shgate_w);
    gateup_merged_kernel<<<GU_BLKS, 256, DYN_SMEM>>>(x, w_gate, w_up, shw_gate, shw_up);
    down_merged_kernel<<<DN_BLKS, 256, DYN_SMEM>>>(w_down, shw_down, out);
}